// round 3
// baseline (speedup 1.0000x reference)
#include <cuda_runtime.h>
#include <cuda_bf16.h>

// MSDeformAttn on GB300 (sm_103a) — branch-free gather version
//   B=2, Hd=8, C=32, P=4, levels=4
//   SHAPES = [(100,150),(50,75),(25,38),(13,19)], L = Q = 19947
//
// One warp per (b,q,h). Lanes: 4 groups x 8 lanes.
//   group g = point index, sub s = channel quad (float4) -> each corner
//   load is one fully-used 128B line per group.
// All 16 corner loads per level-loop are UNCONDITIONAL (clamped indices);
// out-of-bounds corners are zeroed through the bilinear weights, matching
// the reference's clip+valid-mask semantics. Straight-line body lets ptxas
// front-batch loads for high MLP.

#define QTOT 19947
#define LTOT 19947
#define HD   8
#define CH   32
#define ROWF4 (HD * CH / 4)   // float4s between spatial positions = 64

__global__ void __launch_bounds__(256, 4)
msda_kernel(const float* __restrict__ value,
            const float* __restrict__ loc,
            const float* __restrict__ attw,
            float* __restrict__ out)
{
    const int warp = threadIdx.x >> 5;
    const int lane = threadIdx.x & 31;
    const int q = blockIdx.x * 8 + warp;
    if (q >= QTOT) return;                 // uniform across warp

    const int bh = blockIdx.y;             // b*8 + h
    const int b  = bh >> 3;
    const int h  = bh & 7;

    const int group = lane >> 3;           // point index within each level
    const int sub   = lane & 7;            // channel quad

    // ---- per-warp scalar data: one 128B + one 64B coalesced load ----
    const int qbh = (b * QTOT + q) * HD + h;
    const float lv = loc[(size_t)qbh * 32 + lane];                 // (l,p,xy)
    const float wv = (lane < 16) ? attw[(size_t)qbh * 16 + lane] : 0.0f;

    const int Hs[4] = {100, 50, 25, 13};
    const int Ws[4] = {150, 75, 38, 19};
    const int Ss[4] = {0, 15000, 18750, 19700};

    // per-lane base: (b, h, channel-quad), float4 granularity, 32-bit offsets after this
    const float4* vbase = (const float4*)(value + ((size_t)b * LTOT) * (HD * CH)
                                                + (size_t)h * CH) + sub;

    float4 acc = make_float4(0.f, 0.f, 0.f, 0.f);

#pragma unroll
    for (int l = 0; l < 4; ++l) {
        const int Hh = Hs[l];
        const int Ww = Ws[l];
        const int lp = l * 4 + group;

        float x  = __shfl_sync(0xffffffffu, lv, lp * 2);
        float y  = __shfl_sync(0xffffffffu, lv, lp * 2 + 1);
        float wt = __shfl_sync(0xffffffffu, wv, lp);

        x = x * (float)Ww - 0.5f;
        y = y * (float)Hh - 0.5f;
        const float xf = floorf(x);
        const float yf = floorf(y);
        const float dx = x - xf;
        const float dy = y - yf;
        const int x0 = (int)xf;            // in [-1, Ww-1] for uniform locs
        const int y0 = (int)yf;            // in [-1, Hh-1]

        // validity folded into weights ((unsigned) trick: >=0 && <W in one cmp)
        const float fx0 = ((unsigned)x0       < (unsigned)Ww) ? 1.f : 0.f;
        const float fx1 = ((unsigned)(x0 + 1) < (unsigned)Ww) ? 1.f : 0.f;
        const float fy0 = ((unsigned)y0       < (unsigned)Hh) ? 1.f : 0.f;
        const float fy1 = ((unsigned)(y0 + 1) < (unsigned)Hh) ? 1.f : 0.f;

        const float gy0 = wt * (1.f - dy) * fy0;
        const float gy1 = wt * dy * fy1;
        const float gx0 = (1.f - dx) * fx0;
        const float gx1 = dx * fx1;
        const float w00 = gy0 * gx0;
        const float w01 = gy0 * gx1;
        const float w10 = gy1 * gx0;
        const float w11 = gy1 * gx1;

        // clamped indices (x0 <= Ww-1 and y0 <= Hh-1 always hold)
        const int x0c = max(x0, 0);
        const int x1c = min(x0 + 1, Ww - 1);
        const int y0c = max(y0, 0);
        const int y1c = min(y0 + 1, Hh - 1);

        const float4* lb = vbase + Ss[l] * ROWF4;
        const int r00 = (y0c * Ww + x0c) * ROWF4;
        const int r01 = (y0c * Ww + x1c) * ROWF4;
        const int r10 = (y1c * Ww + x0c) * ROWF4;
        const int r11 = (y1c * Ww + x1c) * ROWF4;

        const float4 v00 = lb[r00];
        const float4 v01 = lb[r01];
        const float4 v10 = lb[r10];
        const float4 v11 = lb[r11];

        acc.x += w00 * v00.x; acc.y += w00 * v00.y; acc.z += w00 * v00.z; acc.w += w00 * v00.w;
        acc.x += w01 * v01.x; acc.y += w01 * v01.y; acc.z += w01 * v01.z; acc.w += w01 * v01.w;
        acc.x += w10 * v10.x; acc.y += w10 * v10.y; acc.z += w10 * v10.z; acc.w += w10 * v10.w;
        acc.x += w11 * v11.x; acc.y += w11 * v11.y; acc.z += w11 * v11.z; acc.w += w11 * v11.w;
    }

    // ---- reduce the 4 point-groups (lanes s, s+8, s+16, s+24) ----
    acc.x += __shfl_xor_sync(0xffffffffu, acc.x, 8);
    acc.y += __shfl_xor_sync(0xffffffffu, acc.y, 8);
    acc.z += __shfl_xor_sync(0xffffffffu, acc.z, 8);
    acc.w += __shfl_xor_sync(0xffffffffu, acc.w, 8);
    acc.x += __shfl_xor_sync(0xffffffffu, acc.x, 16);
    acc.y += __shfl_xor_sync(0xffffffffu, acc.y, 16);
    acc.z += __shfl_xor_sync(0xffffffffu, acc.z, 16);
    acc.w += __shfl_xor_sync(0xffffffffu, acc.w, 16);

    if (group == 0) {
        *(float4*)(out + (size_t)qbh * CH + sub * 4) = acc;
    }
}

extern "C" void kernel_launch(void* const* d_in, const int* in_sizes, int n_in,
                              void* d_out, int out_size)
{
    const float* value = (const float*)d_in[0];
    const float* loc   = (const float*)d_in[3];
    const float* attw  = (const float*)d_in[4];
    float* out = (float*)d_out;

    dim3 grid((QTOT + 7) / 8, 2 * HD, 1);
    msda_kernel<<<grid, 256>>>(value, loc, attw, out);
}

// round 4
// speedup vs baseline: 1.1573x; 1.1573x over previous
#include <cuda_runtime.h>
#include <cuda_bf16.h>

// MSDeformAttn on GB300 (sm_103a) — branch-free gather, occupancy-protected
//   B=2, Hd=8, C=32, P=4, levels=4
//   SHAPES = [(100,150),(50,75),(25,38),(13,19)], L = Q = 19947
//
// One warp per (b,q,h). Lanes: 4 groups x 8 lanes.
//   group g = point index, sub s = channel quad (float4) -> each corner
//   load is one fully-used 128B line per group.
// Corner loads are UNCONDITIONAL (clamped indices); out-of-bounds corners are
// zeroed through the bilinear weights (reference clip+mask semantics).
// __launch_bounds__(256,6) caps regs at ~42: enough to batch one level's
// 4 loads (MLP=4/lane, 16/warp-group) but stops cross-level pipelining that
// blew up registers and killed occupancy in the previous round.

#define QTOT 19947
#define LTOT 19947
#define HD   8
#define CH   32
#define ROWF4 (HD * CH / 4)   // float4s between spatial positions = 64

__global__ void __launch_bounds__(256, 6)
msda_kernel(const float* __restrict__ value,
            const float* __restrict__ loc,
            const float* __restrict__ attw,
            float* __restrict__ out)
{
    const int warp = threadIdx.x >> 5;
    const int lane = threadIdx.x & 31;
    const int q = blockIdx.x * 8 + warp;
    if (q >= QTOT) return;                 // uniform across warp

    const int bh = blockIdx.y;             // b*8 + h
    const int b  = bh >> 3;
    const int h  = bh & 7;

    const int group = lane >> 3;           // point index within each level
    const int sub   = lane & 7;            // channel quad

    // ---- per-warp scalar data: one 128B + one 64B coalesced load ----
    const int qbh = (b * QTOT + q) * HD + h;
    const float lv = loc[(size_t)qbh * 32 + lane];                 // (l,p,xy)
    const float wv = (lane < 16) ? attw[(size_t)qbh * 16 + lane] : 0.0f;

    const int Hs[4] = {100, 50, 25, 13};
    const int Ws[4] = {150, 75, 38, 19};
    const int Ss[4] = {0, 15000, 18750, 19700};

    // per-lane base: (b, h, channel-quad); 32-bit offsets from here on
    const float4* vbase = (const float4*)(value + ((size_t)b * LTOT) * (HD * CH)
                                                + (size_t)h * CH) + sub;

    float4 acc = make_float4(0.f, 0.f, 0.f, 0.f);

#pragma unroll
    for (int l = 0; l < 4; ++l) {
        const int Hh = Hs[l];
        const int Ww = Ws[l];
        const int lp = l * 4 + group;

        float x  = __shfl_sync(0xffffffffu, lv, lp * 2);
        float y  = __shfl_sync(0xffffffffu, lv, lp * 2 + 1);
        const float wt = __shfl_sync(0xffffffffu, wv, lp);

        x = x * (float)Ww - 0.5f;
        y = y * (float)Hh - 0.5f;
        const float xf = floorf(x);
        const float yf = floorf(y);
        const float dx = x - xf;
        const float dy = y - yf;
        const int x0 = (int)xf;            // in [-1, Ww-1] for uniform locs
        const int y0 = (int)yf;            // in [-1, Hh-1]

        // validity folded into weights ((unsigned) trick: >=0 && <W in one cmp)
        const float fx0 = ((unsigned)x0       < (unsigned)Ww) ? 1.f : 0.f;
        const float fx1 = ((unsigned)(x0 + 1) < (unsigned)Ww) ? 1.f : 0.f;
        const float fy0 = ((unsigned)y0       < (unsigned)Hh) ? 1.f : 0.f;
        const float fy1 = ((unsigned)(y0 + 1) < (unsigned)Hh) ? 1.f : 0.f;

        const float gy0 = wt * (1.f - dy) * fy0;
        const float gy1 = wt * dy * fy1;
        const float gx0 = (1.f - dx) * fx0;
        const float gx1 = dx * fx1;
        const float w00 = gy0 * gx0;
        const float w01 = gy0 * gx1;
        const float w10 = gy1 * gx0;
        const float w11 = gy1 * gx1;

        // clamped indices (x0 <= Ww-1 and y0 <= Hh-1 always hold)
        const int x0c = max(x0, 0);
        const int x1c = min(x0 + 1, Ww - 1);
        const int y0c = max(y0, 0);
        const int y1c = min(y0 + 1, Hh - 1);

        const float4* lb = vbase + Ss[l] * ROWF4;
        const int r00 = (y0c * Ww + x0c) * ROWF4;
        const int r01 = (y0c * Ww + x1c) * ROWF4;
        const int r10 = (y1c * Ww + x0c) * ROWF4;
        const int r11 = (y1c * Ww + x1c) * ROWF4;

        // batch all 4 corner loads (MLP), then accumulate
        const float4 v00 = lb[r00];
        const float4 v01 = lb[r01];
        const float4 v10 = lb[r10];
        const float4 v11 = lb[r11];

        acc.x += w00 * v00.x; acc.y += w00 * v00.y; acc.z += w00 * v00.z; acc.w += w00 * v00.w;
        acc.x += w01 * v01.x; acc.y += w01 * v01.y; acc.z += w01 * v01.z; acc.w += w01 * v01.w;
        acc.x += w10 * v10.x; acc.y += w10 * v10.y; acc.z += w10 * v10.z; acc.w += w10 * v10.w;
        acc.x += w11 * v11.x; acc.y += w11 * v11.y; acc.z += w11 * v11.z; acc.w += w11 * v11.w;
    }

    // ---- reduce the 4 point-groups (lanes s, s+8, s+16, s+24) ----
    acc.x += __shfl_xor_sync(0xffffffffu, acc.x, 8);
    acc.y += __shfl_xor_sync(0xffffffffu, acc.y, 8);
    acc.z += __shfl_xor_sync(0xffffffffu, acc.z, 8);
    acc.w += __shfl_xor_sync(0xffffffffu, acc.w, 8);
    acc.x += __shfl_xor_sync(0xffffffffu, acc.x, 16);
    acc.y += __shfl_xor_sync(0xffffffffu, acc.y, 16);
    acc.z += __shfl_xor_sync(0xffffffffu, acc.z, 16);
    acc.w += __shfl_xor_sync(0xffffffffu, acc.w, 16);

    if (group == 0) {
        *(float4*)(out + (size_t)qbh * CH + sub * 4) = acc;
    }
}

extern "C" void kernel_launch(void* const* d_in, const int* in_sizes, int n_in,
                              void* d_out, int out_size)
{
    const float* value = (const float*)d_in[0];
    const float* loc   = (const float*)d_in[3];
    const float* attw  = (const float*)d_in[4];
    float* out = (float*)d_out;

    dim3 grid((QTOT + 7) / 8, 2 * HD, 1);
    msda_kernel<<<grid, 256>>>(value, loc, attw, out);
}